// round 4
// baseline (speedup 1.0000x reference)
#include <cuda_runtime.h>
#include <cstdint>

// ---------------- problem constants ----------------
#define BATCH   16
#define N1      4096
#define N2      1024
#define C2      256
#define OUTCH   256
#define KTOT    4096
#define SPLITK  4
#define KPER    (KTOT/SPLITK)   // 1024
#define KT      32              // K tile
#define NT      (KPER/KT)       // 32 tiles
#define BN_EPS  1e-5f

// smem layout (floats)
#define WS_STRIDE 36
#define BS_STRIDE 132
#define WS_BUF    (256*WS_STRIDE)          // 9216 floats per buffer
#define BS_BUF    (32*BS_STRIDE)           // 4224 floats per buffer
#define OFF_WS0   0
#define OFF_WS1   WS_BUF
#define OFF_BS0   (2*WS_BUF)
#define OFF_BS1   (2*WS_BUF + BS_BUF)
#define OFF_IDX   (2*WS_BUF + 2*BS_BUF)          // 1024*3 ints
#define OFF_WGT   (OFF_IDX + KPER*3)             // 1024*3 floats
#define SMEM_FLOATS (OFF_WGT + KPER*3)           // 33024 floats = 132096 B

// ---------------- device scratch ----------------
__device__ int    g_idx[BATCH * N1 * 3];
__device__ float  g_w  [BATCH * N1 * 3];
__device__ float  g_Wtf[(size_t)OUTCH * KTOT];                 // 4 MB tf32-rounded W
__device__ float  g_yp[SPLITK][(size_t)BATCH * OUTCH * C2];    // 16 MB partials
__device__ float  g_y [(size_t)BATCH * OUTCH * C2];
__device__ float  g_sum[C2];
__device__ float  g_sumsq[C2];

// ---------------- helpers ----------------
__device__ __forceinline__ uint32_t smem_u32(const void* p) {
    uint32_t a;
    asm("{ .reg .u64 t; cvta.to.shared.u64 t, %1; cvt.u32.u64 %0, t; }" : "=r"(a) : "l"(p));
    return a;
}
__device__ __forceinline__ float tf32r(float x) {
    uint32_t u;
    asm("cvt.rna.tf32.f32 %0, %1;" : "=r"(u) : "f"(x));
    return __uint_as_float(u);
}
__device__ __forceinline__ void cp16(uint32_t dst, const void* src) {
    asm volatile("cp.async.cg.shared.global [%0], [%1], 16;" :: "r"(dst), "l"(src) : "memory");
}
#define CP_COMMIT()  asm volatile("cp.async.commit_group;" ::: "memory")
#define CP_WAIT(n)   asm volatile("cp.async.wait_group %0;" :: "n"(n) : "memory")

__device__ __forceinline__ void mma_tf32(float* d, const uint32_t* a, const uint32_t* b) {
    asm volatile(
        "mma.sync.aligned.m16n8k8.row.col.f32.tf32.tf32.f32 "
        "{%0,%1,%2,%3}, {%4,%5,%6,%7}, {%8,%9}, {%0,%1,%2,%3};"
        : "+f"(d[0]), "+f"(d[1]), "+f"(d[2]), "+f"(d[3])
        : "r"(a[0]), "r"(a[1]), "r"(a[2]), "r"(a[3]), "r"(b[0]), "r"(b[1]));
}

__device__ __forceinline__ void sts_tf32x4(uint32_t addr, float4 v) {
    uint32_t a, b, c, d;
    asm volatile("cvt.rna.tf32.f32 %0, %1;" : "=r"(a) : "f"(v.x));
    asm volatile("cvt.rna.tf32.f32 %0, %1;" : "=r"(b) : "f"(v.y));
    asm volatile("cvt.rna.tf32.f32 %0, %1;" : "=r"(c) : "f"(v.z));
    asm volatile("cvt.rna.tf32.f32 %0, %1;" : "=r"(d) : "f"(v.w));
    asm volatile("st.shared.v4.b32 [%0], {%1, %2, %3, %4};"
                 :: "r"(addr), "r"(a), "r"(b), "r"(c), "r"(d) : "memory");
}

// ---------------- kernel 0: zero BN accumulators ----------------
__global__ void zero_stats_kernel() {
    int c = threadIdx.x;
    g_sum[c] = 0.f;
    g_sumsq[c] = 0.f;
}

// ---------------- kernel 0b: W -> tf32-rounded copy ----------------
__global__ void convW_kernel(const float* __restrict__ W1) {
    int i = blockIdx.x * 256 + threadIdx.x;
    float4 v = ((const float4*)W1)[i];
    ((float4*)g_Wtf)[i] = make_float4(tf32r(v.x), tf32r(v.y), tf32r(v.z), tf32r(v.w));
}

// ---------------- kernel 1: 3-NN + weights (2 points / thread) ----------------
__global__ __launch_bounds__(256)
void topk_kernel(const float* __restrict__ xyz1,
                 const float* __restrict__ xyz2) {
    __shared__ float sx[N2], sy[N2], sz[N2];
    int b = blockIdx.x >> 3;
    int chunk = blockIdx.x & 7;

    const float* p2 = xyz2 + (size_t)b * N2 * 3;
    for (int j = threadIdx.x; j < N2; j += 256) {
        sx[j] = p2[j * 3 + 0]; sy[j] = p2[j * 3 + 1]; sz[j] = p2[j * 3 + 2];
    }
    __syncthreads();

    int nA = chunk * 512 + threadIdx.x;
    int nB = nA + 256;
    const float* pA = xyz1 + ((size_t)b * N1 + nA) * 3;
    const float* pB = xyz1 + ((size_t)b * N1 + nB) * 3;
    float ax = pA[0], ay = pA[1], az = pA[2];
    float bx = pB[0], by = pB[1], bz = pB[2];

    float a0 = 3.4e38f, a1 = 3.4e38f, a2 = 3.4e38f;
    int   ai0 = 0, ai1 = 0, ai2 = 0;
    float b0 = 3.4e38f, b1 = 3.4e38f, b2 = 3.4e38f;
    int   bi0 = 0, bi1 = 0, bi2 = 0;

#pragma unroll 4
    for (int j = 0; j < N2; ++j) {
        float qx = sx[j], qy = sy[j], qz = sz[j];
        float dx = ax - qx, dy = ay - qy, dz = az - qz;
        float dA = fmaf(dx, dx, fmaf(dy, dy, dz * dz));
        float ex = bx - qx, ey = by - qy, ez = bz - qz;
        float dB = fmaf(ex, ex, fmaf(ey, ey, ez * ez));
        if (dA < a2) {
            if (dA < a1) {
                a2 = a1; ai2 = ai1;
                if (dA < a0) { a1 = a0; ai1 = ai0; a0 = dA; ai0 = j; }
                else         { a1 = dA; ai1 = j; }
            } else { a2 = dA; ai2 = j; }
        }
        if (dB < b2) {
            if (dB < b1) {
                b2 = b1; bi2 = bi1;
                if (dB < b0) { b1 = b0; bi1 = bi0; b0 = dB; bi0 = j; }
                else         { b1 = dB; bi1 = j; }
            } else { b2 = dB; bi2 = j; }
        }
    }
    {
        float r0 = 1.f / (a0 + 1e-8f), r1 = 1.f / (a1 + 1e-8f), r2 = 1.f / (a2 + 1e-8f);
        float inv = 1.f / (r0 + r1 + r2);
        size_t base = ((size_t)b * N1 + nA) * 3;
        g_idx[base + 0] = ai0; g_idx[base + 1] = ai1; g_idx[base + 2] = ai2;
        g_w  [base + 0] = r0 * inv; g_w[base + 1] = r1 * inv; g_w[base + 2] = r2 * inv;
    }
    {
        float r0 = 1.f / (b0 + 1e-8f), r1 = 1.f / (b1 + 1e-8f), r2 = 1.f / (b2 + 1e-8f);
        float inv = 1.f / (r0 + r1 + r2);
        size_t base = ((size_t)b * N1 + nB) * 3;
        g_idx[base + 0] = bi0; g_idx[base + 1] = bi1; g_idx[base + 2] = bi2;
        g_w  [base + 0] = r0 * inv; g_w[base + 1] = r1 * inv; g_w[base + 2] = r2 * inv;
    }
}

// ---------------- kernel 2: fused interp + tf32 mma GEMM ----------------
// grid = b(16) x Ntile(2) x splitK(4) = 128 CTAs, 512 threads (16 warps)
// CTA computes Y[b][0:256][c0:c0+128] partial over K range [k0,k0+1024)
__global__ __launch_bounds__(512, 1)
void gemm_fused_kernel(const float* __restrict__ x2) {
    extern __shared__ float sm[];
    const uint32_t smb = smem_u32(sm);
    int*   sIdx = (int*)(sm + OFF_IDX);
    float* sWgt = sm + OFF_WGT;

    int bid = blockIdx.x;
    int s   = bid & 3;
    int ntb = (bid >> 2) & 1;
    int b   = bid >> 3;
    int c0 = ntb * 128, k0 = s * KPER;

    int t = threadIdx.x;
    int w = t >> 5, lane = t & 31;
    int g = lane >> 2, kq = lane & 3;
    int warp_m = (w & 7) * 32;
    int warp_n = (w >> 3) * 64;

    const float* Wg = g_Wtf + k0;
    const float* xb = x2 + (size_t)b * N2 * C2 + c0;

    // W cp.async slots: 256 rows x 8 float4 = 2048, 4 per thread
    int wm[4], wq4[4];
    uint32_t wdst[4];
#pragma unroll
    for (int i = 0; i < 4; ++i) {
        int li = i * 512 + t;
        wm[i]  = li >> 3;
        wq4[i] = (li & 7) * 4;
        wdst[i] = (uint32_t)((wm[i] * WS_STRIDE + wq4[i]) * 4);
    }

    // B gather mapping: row r (0..31), cols cc, cc+4 (local to 128-wide tile)
    int br = t >> 4;
    int bc = (t & 15) * 8;
    uint32_t bdst0 = (uint32_t)((OFF_BS0 + br * BS_STRIDE + bc) * 4);

    // preload idx/weights for this CTA's K-range, issue first W cp
#pragma unroll
    for (int i = 0; i < 4; ++i)
        cp16(smb + OFF_WS0 * 4 + wdst[i], Wg + (size_t)wm[i] * KTOT + wq4[i]);
    CP_COMMIT();
    for (int j = t; j < KPER; j += 512) {
        size_t gb = ((size_t)b * N1 + k0 + j) * 3;
        sIdx[j * 3 + 0] = g_idx[gb + 0];
        sIdx[j * 3 + 1] = g_idx[gb + 1];
        sIdx[j * 3 + 2] = g_idx[gb + 2];
        sWgt[j * 3 + 0] = g_w[gb + 0];
        sWgt[j * 3 + 1] = g_w[gb + 1];
        sWgt[j * 3 + 2] = g_w[gb + 2];
    }
    __syncthreads();

    // gather B tile 0 into registers
    float4 rv[6];
    float  rw0, rw1, rw2;
    {
        int row = br;   // tile 0
        int i0 = sIdx[row * 3 + 0], i1 = sIdx[row * 3 + 1], i2 = sIdx[row * 3 + 2];
        rw0 = sWgt[row * 3 + 0]; rw1 = sWgt[row * 3 + 1]; rw2 = sWgt[row * 3 + 2];
        const float* r0 = xb + (size_t)i0 * C2 + bc;
        const float* r1 = xb + (size_t)i1 * C2 + bc;
        const float* r2 = xb + (size_t)i2 * C2 + bc;
        rv[0] = *(const float4*)(r0);     rv[1] = *(const float4*)(r0 + 4);
        rv[2] = *(const float4*)(r1);     rv[3] = *(const float4*)(r1 + 4);
        rv[4] = *(const float4*)(r2);     rv[5] = *(const float4*)(r2 + 4);
    }

    float acc[2][8][4];
#pragma unroll
    for (int mt = 0; mt < 2; ++mt)
#pragma unroll
        for (int nt = 0; nt < 8; ++nt)
#pragma unroll
            for (int r = 0; r < 4; ++r) acc[mt][nt][r] = 0.f;

    for (int kt = 0; kt < NT; ++kt) {
        int cur = kt & 1;
        CP_WAIT(0);
        // combine gathered regs -> B tile (tf32) in smem
        uint32_t bd = (cur ? (uint32_t)((OFF_BS1 - OFF_BS0) * 4) : 0u) + bdst0 + smb;
        {
            float4 o0, o1;
            o0.x = fmaf(rw0, rv[0].x, fmaf(rw1, rv[2].x, rw2 * rv[4].x));
            o0.y = fmaf(rw0, rv[0].y, fmaf(rw1, rv[2].y, rw2 * rv[4].y));
            o0.z = fmaf(rw0, rv[0].z, fmaf(rw1, rv[2].z, rw2 * rv[4].z));
            o0.w = fmaf(rw0, rv[0].w, fmaf(rw1, rv[2].w, rw2 * rv[4].w));
            o1.x = fmaf(rw0, rv[1].x, fmaf(rw1, rv[3].x, rw2 * rv[5].x));
            o1.y = fmaf(rw0, rv[1].y, fmaf(rw1, rv[3].y, rw2 * rv[5].y));
            o1.z = fmaf(rw0, rv[1].z, fmaf(rw1, rv[3].z, rw2 * rv[5].z));
            o1.w = fmaf(rw0, rv[1].w, fmaf(rw1, rv[3].w, rw2 * rv[5].w));
            sts_tf32x4(bd, o0);
            sts_tf32x4(bd + 16, o1);
        }
        __syncthreads();

        if (kt + 1 < NT) {
            int nxt = (kt + 1) & 1;
            int kg = (kt + 1) * KT;
            uint32_t woff = (uint32_t)((nxt ? OFF_WS1 : OFF_WS0) * 4);
#pragma unroll
            for (int i = 0; i < 4; ++i)
                cp16(smb + woff + wdst[i], Wg + (size_t)wm[i] * KTOT + kg + wq4[i]);
            CP_COMMIT();
            // gather next B tile into regs
            int row = kg + br;
            int i0 = sIdx[row * 3 + 0], i1 = sIdx[row * 3 + 1], i2 = sIdx[row * 3 + 2];
            rw0 = sWgt[row * 3 + 0]; rw1 = sWgt[row * 3 + 1]; rw2 = sWgt[row * 3 + 2];
            const float* r0 = xb + (size_t)i0 * C2 + bc;
            const float* r1 = xb + (size_t)i1 * C2 + bc;
            const float* r2 = xb + (size_t)i2 * C2 + bc;
            rv[0] = *(const float4*)(r0);     rv[1] = *(const float4*)(r0 + 4);
            rv[2] = *(const float4*)(r1);     rv[3] = *(const float4*)(r1 + 4);
            rv[4] = *(const float4*)(r2);     rv[5] = *(const float4*)(r2 + 4);
        }

        const float* Ws = sm + (cur ? OFF_WS1 : OFF_WS0);
        const float* Bs = sm + (cur ? OFF_BS1 : OFF_BS0);
#pragma unroll
        for (int ks = 0; ks < 4; ++ks) {
            int kb = ks * 8;
            uint32_t a[2][4], bb[8][2];
#pragma unroll
            for (int mt = 0; mt < 2; ++mt) {
                const float* ab = Ws + (warp_m + mt * 16 + g) * WS_STRIDE + kb + kq;
                a[mt][0] = __float_as_uint(ab[0]);
                a[mt][1] = __float_as_uint(ab[8 * WS_STRIDE]);
                a[mt][2] = __float_as_uint(ab[4]);
                a[mt][3] = __float_as_uint(ab[8 * WS_STRIDE + 4]);
            }
#pragma unroll
            for (int nt = 0; nt < 8; ++nt) {
                const float* bbp = Bs + (kb + kq) * BS_STRIDE + warp_n + nt * 8 + g;
                bb[nt][0] = __float_as_uint(bbp[0]);
                bb[nt][1] = __float_as_uint(bbp[4 * BS_STRIDE]);
            }
#pragma unroll
            for (int mt = 0; mt < 2; ++mt)
#pragma unroll
                for (int nt = 0; nt < 8; ++nt)
                    mma_tf32(acc[mt][nt], a[mt], bb[nt]);
        }
        __syncthreads();
    }

    // epilogue -> g_yp[s]
    float* out = g_yp[s] + (size_t)b * OUTCH * C2 + c0;
#pragma unroll
    for (int mt = 0; mt < 2; ++mt) {
        int r0 = warp_m + mt * 16 + g;
#pragma unroll
        for (int nt = 0; nt < 8; ++nt) {
            int col = warp_n + nt * 8 + kq * 2;
            *(float2*)(out + (size_t)r0 * C2 + col)       = make_float2(acc[mt][nt][0], acc[mt][nt][1]);
            *(float2*)(out + (size_t)(r0 + 8) * C2 + col) = make_float2(acc[mt][nt][2], acc[mt][nt][3]);
        }
    }
}

// ---------------- kernel 4: reduce partials + bias + BN stats ----------------
__global__ void reduce_kernel(const float* __restrict__ b1) {
    int c = threadIdx.x;
    int row0 = blockIdx.x * 16;
    float s1 = 0.f, s2 = 0.f;
    for (int r = 0; r < 16; ++r) {
        int row = row0 + r;
        int o = row & (OUTCH - 1);
        size_t idx = (size_t)row * C2 + c;
        float v = b1[o];
#pragma unroll
        for (int s = 0; s < SPLITK; ++s) v += g_yp[s][idx];
        g_y[idx] = v;
        s1 += v;
        s2 = fmaf(v, v, s2);
    }
    atomicAdd(&g_sum[c], s1);
    atomicAdd(&g_sumsq[c], s2);
}

// ---------------- kernel 5: BN + ReLU ----------------
__global__ void bn_kernel(const float* __restrict__ gamma,
                          const float* __restrict__ beta,
                          float* __restrict__ out) {
    int c = threadIdx.x;
    int row = blockIdx.x;
    const float invN = 1.f / (BATCH * OUTCH);
    float mean = g_sum[c] * invN;
    float var  = fmaf(g_sumsq[c], invN, -mean * mean);
    float rstd = rsqrtf(var + BN_EPS);
    float v = g_y[(size_t)row * C2 + c];
    float r = fmaf(gamma[c] * rstd, v - mean, beta[c]);
    out[(size_t)row * C2 + c] = fmaxf(r, 0.f);
}

// ---------------- launcher ----------------
extern "C" void kernel_launch(void* const* d_in, const int* in_sizes, int n_in,
                              void* d_out, int out_size) {
    const float* x2    = (const float*)d_in[1];
    const float* xyz1  = (const float*)d_in[2];
    const float* xyz2  = (const float*)d_in[3];
    const float* W1    = (const float*)d_in[4];
    const float* b1    = (const float*)d_in[5];
    const float* gamma = (const float*)d_in[6];
    const float* beta  = (const float*)d_in[7];
    float* out = (float*)d_out;

    cudaFuncSetAttribute(gemm_fused_kernel,
                         cudaFuncAttributeMaxDynamicSharedMemorySize,
                         SMEM_FLOATS * 4);

    zero_stats_kernel<<<1, C2>>>();
    convW_kernel<<<(OUTCH * KTOT) / 1024, 256>>>(W1);
    topk_kernel<<<BATCH * 8, 256>>>(xyz1, xyz2);
    gemm_fused_kernel<<<BATCH * 2 * SPLITK, 512, SMEM_FLOATS * 4>>>(x2);
    reduce_kernel<<<(BATCH * OUTCH) / 16, C2>>>(b1);
    bn_kernel<<<BATCH * OUTCH, C2>>>(gamma, beta, out);
}